// round 1
// baseline (speedup 1.0000x reference)
#include <cuda_runtime.h>

// SSIM loss, 7x7 valid box window, inputs [32,3,512,512] fp32, scalar output.
//
// Single fused pass: per-CTA band of 56 output rows x full 512-wide image plane.
// Vertical 7-row running sums per thread (thread = column), staged to SMEM in
// 8-row chunks; horizontal 7-wide sliding window (8 outputs per thread) + SSIM
// pointwise + hierarchical reduction. No intermediate HBM traffic.

#define WINR   7
#define IW     512
#define IH     512
#define OW     506
#define OH     506
#define BR     56          // output rows per band (7 chunks of 8)
#define NCHUNK 7
#define NBANDS 10          // ceil(506/56)
#define NIMG   96          // 32 batch * 3 channels
#define RS     519         // smem row stride (odd -> conflict-free horizontal reads)
#define PLANE  (8 * RS)    // one quantity plane: 8 rows staged
#define SMEM_BYTES (5 * PLANE * 4)

__device__ float g_partials[NBANDS * NIMG];

__device__ __forceinline__ float ssim_term(float sx, float sy, float sxx,
                                           float syy, float sxy) {
    // Constants folded: C1=(0.01)^2, C2=(0.03)^2, window N=49, cov_norm=49/48.
    // A1/B1 scaled by 2401, A2/B2 scaled by 2352; scales cancel in the ratio.
    const float c1big = 0.2401f;   // 2401 * C1
    const float c2big = 2.1168f;   // 2352 * C2
    float t1 = sx * sy;
    float a1 = fmaf(t1, 2.0f, c1big);
    float b1 = fmaf(sx, sx, c1big);
    b1 = fmaf(sy, sy, b1);
    float a2 = fmaf(sxy, 98.0f, c2big);
    a2 = fmaf(t1, -2.0f, a2);
    float s4 = sxx + syy;
    float b2 = fmaf(s4, 49.0f, c2big);
    b2 = fmaf(sx, -sx, b2);
    b2 = fmaf(sy, -sy, b2);
    return __fdividef(a1 * a2, b1 * b2);
}

__global__ __launch_bounds__(512, 2)
void ssim_main_kernel(const float* __restrict__ X, const float* __restrict__ Y) {
    extern __shared__ float sm[];  // [5][8][RS]
    const int tid  = threadIdx.x;
    const int band = blockIdx.x;
    const int img  = blockIdx.y;

    const float* __restrict__ xp = X + (size_t)img * (IH * IW);
    const float* __restrict__ yp = Y + (size_t)img * (IH * IW);
    const int r0  = band * BR;
    const int col = tid;

    // ---- vertical running sums (rows r0..r0+5 prologue) ----
    float Vx = 0.f, Vy = 0.f, Vxx = 0.f, Vyy = 0.f, Vxy = 0.f;
#pragma unroll
    for (int k = 0; k < 6; ++k) {
        float x = xp[(r0 + k) * IW + col];
        float y = yp[(r0 + k) * IW + col];
        Vx += x; Vy += y;
        Vxx = fmaf(x, x, Vxx);
        Vyy = fmaf(y, y, Vyy);
        Vxy = fmaf(x, y, Vxy);
    }

    float acc = 0.f;

    const int jrow = tid & 7;   // horizontal-phase row within chunk
    const int grp  = tid >> 3;  // horizontal-phase column group (0..63)
    const int c0   = grp * 8;

    for (int chunk = 0; chunk < NCHUNK; ++chunk) {
        const int rb = r0 + chunk * 8;

        // ---- vertical: advance 8 rows, stage column sums to smem ----
#pragma unroll
        for (int j = 0; j < 8; ++j) {
            int r = rb + j;
            if (r < OH) {
                float xn = xp[(r + 6) * IW + col];
                float yn = yp[(r + 6) * IW + col];
                Vx += xn; Vy += yn;
                Vxx = fmaf(xn, xn, Vxx);
                Vyy = fmaf(yn, yn, Vyy);
                Vxy = fmaf(xn, yn, Vxy);
                sm[0 * PLANE + j * RS + col] = Vx;
                sm[1 * PLANE + j * RS + col] = Vy;
                sm[2 * PLANE + j * RS + col] = Vxx;
                sm[3 * PLANE + j * RS + col] = Vyy;
                sm[4 * PLANE + j * RS + col] = Vxy;
                // evict oldest row (reload from L1; avoids register ring)
                float xo = xp[r * IW + col];
                float yo = yp[r * IW + col];
                Vx -= xo; Vy -= yo;
                Vxx = fmaf(xo, -xo, Vxx);
                Vyy = fmaf(yo, -yo, Vyy);
                Vxy = fmaf(xo, -yo, Vxy);
            }
        }
        __syncthreads();

        // ---- horizontal: 8 rows x 64 groups = 512 tasks, 7-wide sliding window ----
        {
            int r = rb + jrow;
            if (r < OH) {
                const float* base = sm + jrow * RS + c0;
                float Bx = 0.f, By = 0.f, Bxx = 0.f, Byy = 0.f, Bxy = 0.f;
#pragma unroll
                for (int k = 0; k < 7; ++k) {
                    Bx  += base[0 * PLANE + k];
                    By  += base[1 * PLANE + k];
                    Bxx += base[2 * PLANE + k];
                    Byy += base[3 * PLANE + k];
                    Bxy += base[4 * PLANE + k];
                }
                const int T = (OW - c0 < 8) ? (OW - c0) : 8;
                acc += ssim_term(Bx, By, Bxx, Byy, Bxy);
#pragma unroll
                for (int i = 1; i < 8; ++i) {
                    if (i < T) {
                        Bx  += base[0 * PLANE + 6 + i] - base[0 * PLANE + i - 1];
                        By  += base[1 * PLANE + 6 + i] - base[1 * PLANE + i - 1];
                        Bxx += base[2 * PLANE + 6 + i] - base[2 * PLANE + i - 1];
                        Byy += base[3 * PLANE + 6 + i] - base[3 * PLANE + i - 1];
                        Bxy += base[4 * PLANE + 6 + i] - base[4 * PLANE + i - 1];
                        acc += ssim_term(Bx, By, Bxx, Byy, Bxy);
                    }
                }
            }
        }
        __syncthreads();
    }

    // ---- block reduction ----
    __shared__ float red[512];
    red[tid] = acc;
    __syncthreads();
#pragma unroll
    for (int s = 256; s >= 1; s >>= 1) {
        if (tid < s) red[tid] += red[tid + s];
        __syncthreads();
    }
    if (tid == 0) g_partials[blockIdx.y * gridDim.x + blockIdx.x] = red[0];
}

__global__ void ssim_finalize_kernel(float* __restrict__ out) {
    __shared__ float red[512];
    const int tid = threadIdx.x;
    float s = 0.f;
    for (int i = tid; i < NBANDS * NIMG; i += 512) s += g_partials[i];
    red[tid] = s;
    __syncthreads();
#pragma unroll
    for (int st = 256; st >= 1; st >>= 1) {
        if (tid < st) red[tid] += red[tid + st];
        __syncthreads();
    }
    if (tid == 0) {
        const float inv_n = 1.0f / 24579456.0f;  // 96 * 506 * 506
        out[0] = 1.0f - red[0] * inv_n;
    }
}

extern "C" void kernel_launch(void* const* d_in, const int* in_sizes, int n_in,
                              void* d_out, int out_size) {
    (void)in_sizes; (void)n_in; (void)out_size;
    const float* X = (const float*)d_in[0];
    const float* Y = (const float*)d_in[1];

    cudaFuncSetAttribute(ssim_main_kernel,
                         cudaFuncAttributeMaxDynamicSharedMemorySize, SMEM_BYTES);

    dim3 grid(NBANDS, NIMG);
    ssim_main_kernel<<<grid, 512, SMEM_BYTES>>>(X, Y);
    ssim_finalize_kernel<<<1, 512>>>((float*)d_out);
}

// round 2
// speedup vs baseline: 1.0088x; 1.0088x over previous
#include <cuda_runtime.h>

// SSIM loss, 7x7 valid window, inputs [32,3,512,512] fp32, scalar output.
// Single fused kernel: per-CTA band of 85 output rows x full 512-wide plane.
// Vertical 7-row running column sums per thread (4 quantities: x, y, xx+yy, xy)
// staged to SMEM in 8-row chunks; horizontal 7-wide sliding window (8 outputs
// per thread) + constant-folded SSIM + shuffle reduction + deterministic
// last-block global reduction (no second kernel).

#define IW     512
#define OH     506
#define OW     506
#define BR     85          // output rows per band
#define NCHUNK 11          // ceil(85/8)
#define NBANDS 6           // 6*85 = 510 >= 506
#define NIMG   96          // 32 batch * 3 channels
#define NCTA   (NBANDS * NIMG)   // 576 CTAs = 1.95 waves @ occ 2 on 148 SMs
#define RS     519         // smem row stride (odd -> conflict-free horiz reads)
#define PLANE  (8 * RS)
#define SMEM_BYTES (4 * PLANE * 4)   // 66,432 B -> 2 CTAs/SM

__device__ float g_partials[NCTA];
__device__ unsigned int g_count = 0;

__device__ __forceinline__ float ssim_term(float sx, float sy, float ss, float sxy) {
    // Raw 49-pixel window sums. Scales folded:
    //   A1,B1 x2401; A2,B2 x2352 (48*49). Ratio unchanged.
    const float c1big = 0.2401f;   // 2401 * (0.01)^2
    const float c2big = 2.1168f;   // 2352 * (0.03)^2
    float t1 = sx * sy;
    float a1 = fmaf(t1, 2.0f, c1big);
    float b1 = fmaf(sx, sx, c1big);
    b1 = fmaf(sy, sy, b1);
    float a2 = fmaf(sxy, 98.0f, c2big);
    a2 = fmaf(t1, -2.0f, a2);
    float b2 = fmaf(ss, 49.0f, c2big);
    b2 = fmaf(sx, -sx, b2);
    b2 = fmaf(sy, -sy, b2);
    return __fdividef(a1 * a2, b1 * b2);
}

__global__ __launch_bounds__(512, 2)
void ssim_kernel(const float* __restrict__ X, const float* __restrict__ Y,
                 float* __restrict__ out) {
    extern __shared__ float sm[];  // [4][8][RS]
    __shared__ float wsum[16];
    __shared__ bool isLast;

    const int tid  = threadIdx.x;
    const int band = blockIdx.x;
    const int img  = blockIdx.y;

    const float* __restrict__ xp = X + (size_t)img * (512 * 512);
    const float* __restrict__ yp = Y + (size_t)img * (512 * 512);
    const int r0   = band * BR;
    const int rmax = min(r0 + BR - 1, OH - 1);
    const int col  = tid;

    // ---- vertical running sums: prologue rows r0..r0+5 ----
    float Vx = 0.f, Vy = 0.f, Vs = 0.f, Vxy = 0.f;
#pragma unroll
    for (int k = 0; k < 6; ++k) {
        float x = xp[(r0 + k) * IW + col];
        float y = yp[(r0 + k) * IW + col];
        Vx += x; Vy += y;
        Vs  = fmaf(x, x, Vs);
        Vs  = fmaf(y, y, Vs);
        Vxy = fmaf(x, y, Vxy);
    }

    float acc = 0.f;
    const int jrow = tid & 7;
    const int grp  = tid >> 3;
    const int c0   = grp * 8;

    for (int chunk = 0; chunk < NCHUNK; ++chunk) {
        const int rb = r0 + chunk * 8;
        if (rb > rmax) break;  // uniform per block

        // ---- vertical: advance 8 rows, stage 4 column-sum planes ----
#pragma unroll
        for (int j = 0; j < 8; ++j) {
            int r = rb + j;
            if (r <= rmax) {
                float xn = xp[(r + 6) * IW + col];
                float yn = yp[(r + 6) * IW + col];
                Vx += xn; Vy += yn;
                Vs  = fmaf(xn, xn, Vs);
                Vs  = fmaf(yn, yn, Vs);
                Vxy = fmaf(xn, yn, Vxy);
                sm[0 * PLANE + j * RS + col] = Vx;
                sm[1 * PLANE + j * RS + col] = Vy;
                sm[2 * PLANE + j * RS + col] = Vs;
                sm[3 * PLANE + j * RS + col] = Vxy;
                // evict oldest row (L1-hit reload; avoids register ring)
                float xo = xp[r * IW + col];
                float yo = yp[r * IW + col];
                Vx -= xo; Vy -= yo;
                Vs  = fmaf(xo, -xo, Vs);
                Vs  = fmaf(yo, -yo, Vs);
                Vxy = fmaf(xo, -yo, Vxy);
            }
        }
        __syncthreads();

        // ---- horizontal: 8 rows x 64 groups, 7-wide sliding window ----
        {
            int r = rb + jrow;
            if (r <= rmax) {
                const float* base = sm + jrow * RS + c0;
                float Bx = 0.f, By = 0.f, Bs = 0.f, Bxy = 0.f;
#pragma unroll
                for (int k = 0; k < 7; ++k) {
                    Bx  += base[0 * PLANE + k];
                    By  += base[1 * PLANE + k];
                    Bs  += base[2 * PLANE + k];
                    Bxy += base[3 * PLANE + k];
                }
                acc += ssim_term(Bx, By, Bs, Bxy);
                const int T = (OW - c0 < 8) ? (OW - c0) : 8;
#pragma unroll
                for (int i = 1; i < 8; ++i) {
                    if (i < T) {
                        Bx  += base[0 * PLANE + 6 + i] - base[0 * PLANE + i - 1];
                        By  += base[1 * PLANE + 6 + i] - base[1 * PLANE + i - 1];
                        Bs  += base[2 * PLANE + 6 + i] - base[2 * PLANE + i - 1];
                        Bxy += base[3 * PLANE + 6 + i] - base[3 * PLANE + i - 1];
                        acc += ssim_term(Bx, By, Bs, Bxy);
                    }
                }
            }
        }
        __syncthreads();
    }

    // ---- block reduction: warp shuffle + one smem pass ----
#pragma unroll
    for (int o = 16; o > 0; o >>= 1)
        acc += __shfl_xor_sync(0xffffffffu, acc, o);
    if ((tid & 31) == 0) wsum[tid >> 5] = acc;
    __syncthreads();

    if (tid == 0) {
        float s = 0.f;
#pragma unroll
        for (int w = 0; w < 16; ++w) s += wsum[w];
        g_partials[img * NBANDS + band] = s;
        __threadfence();
        unsigned int old = atomicAdd(&g_count, 1u);
        isLast = (old == NCTA - 1);
    }
    __syncthreads();

    // ---- deterministic last-block global reduction ----
    if (isLast) {
        float s = 0.f;
        for (int i = tid; i < NCTA; i += 512) s += g_partials[i];
#pragma unroll
        for (int o = 16; o > 0; o >>= 1)
            s += __shfl_xor_sync(0xffffffffu, s, o);
        if ((tid & 31) == 0) wsum[tid >> 5] = s;
        __syncthreads();
        if (tid == 0) {
            float t = 0.f;
#pragma unroll
            for (int w = 0; w < 16; ++w) t += wsum[w];
            out[0] = 1.0f - t * (1.0f / 24579456.0f);  // 96*506*506
            g_count = 0;  // reset for next graph replay
        }
    }
}

extern "C" void kernel_launch(void* const* d_in, const int* in_sizes, int n_in,
                              void* d_out, int out_size) {
    (void)in_sizes; (void)n_in; (void)out_size;
    const float* X = (const float*)d_in[0];
    const float* Y = (const float*)d_in[1];

    cudaFuncSetAttribute(ssim_kernel,
                         cudaFuncAttributeMaxDynamicSharedMemorySize, SMEM_BYTES);

    dim3 grid(NBANDS, NIMG);
    ssim_kernel<<<grid, 512, SMEM_BYTES>>>(X, Y, (float*)d_out);
}

// round 3
// speedup vs baseline: 1.4990x; 1.4858x over previous
#include <cuda_runtime.h>

// SSIM loss, 7x7 valid window, [32,3,512,512] fp32 inputs, scalar out.
// Issue-bound kernel -> minimize instructions/output:
//  - vertical running column sums with an 8-slot register ring (no old-row LDG)
//  - SMEM staged as interleaved float2 planes: (Vx,Vy) and (Vxx+Vyy,Vxy)
//  - horizontal 7-wide sliding window fully in f32x2 packed math + LDS.64
//  - unguarded fast path for full 88-row bands; guarded path for the tail band
//  - deterministic single-kernel reduction (last CTA finishes).

#define IW     512
#define OH     506
#define OW     506
#define BR     88
#define NCHUNK 11
#define NBANDS 6
#define NIMG   96
#define NCTA   (NBANDS * NIMG)   // 576
#define RS2    517               // float2 row stride (odd -> conflict-free)
#define PLANE2 (8 * RS2)
#define SMEM_BYTES (2 * PLANE2 * 8)   // 66,176 B -> 2 CTAs/SM

typedef unsigned long long u64;

__device__ float g_partials[NCTA];
__device__ unsigned int g_count = 0;

__device__ __forceinline__ u64 add2(u64 a, u64 b) {
    u64 r; asm("add.rn.f32x2 %0, %1, %2;" : "=l"(r) : "l"(a), "l"(b)); return r;
}
__device__ __forceinline__ u64 fma2(u64 a, u64 b, u64 c) {
    u64 r; asm("fma.rn.f32x2 %0, %1, %2, %3;" : "=l"(r) : "l"(a), "l"(b), "l"(c)); return r;
}
__device__ __forceinline__ void unpack2(u64 v, float& a, float& b) {
    asm("mov.b64 {%0, %1}, %2;" : "=f"(a), "=f"(b) : "l"(v));
}

#define NEG1X2 0xBF800000BF800000ull   // (-1.0f, -1.0f)

__device__ __forceinline__ float ssim_term(float sx, float sy, float ss, float sxy) {
    // Raw 49-pixel window sums; A1,B1 scaled x2401, A2,B2 scaled x2352 (cancels).
    const float c1big = 0.2401f;   // 2401 * (0.01)^2
    const float c2big = 2.1168f;   // 2352 * (0.03)^2
    float t1 = sx * sy;
    float a1 = fmaf(t1, 2.0f, c1big);
    float b1 = fmaf(sx, sx, c1big);
    b1 = fmaf(sy, sy, b1);
    float a2 = fmaf(sxy, 98.0f, c2big);
    a2 = fmaf(t1, -2.0f, a2);
    float b2 = fmaf(ss, 49.0f, c2big);
    b2 = fmaf(sx, -sx, b2);
    b2 = fmaf(sy, -sy, b2);
    return __fdividef(a1 * a2, b1 * b2);
}

template <bool GUARD>
__device__ __forceinline__ float process_band(
    const float* __restrict__ xp, const float* __restrict__ yp,
    float2* __restrict__ sm, int r0, int rmax, int tid) {

    const int col = tid;
    float rx[8], ry[8];                 // ring: value subtracted 6 steps later
    float Vx = 0.f, Vy = 0.f, Vs = 0.f, Vxy = 0.f;

    // prologue rows r0..r0+5 -> ring slots 2..7
#pragma unroll
    for (int k = 0; k < 6; ++k) {
        float x = xp[(r0 + k) * IW + col];
        float y = yp[(r0 + k) * IW + col];
        Vx += x; Vy += y;
        Vs  = fmaf(x, x, Vs);
        Vs  = fmaf(y, y, Vs);
        Vxy = fmaf(x, y, Vxy);
        rx[k + 2] = x; ry[k + 2] = y;
    }

    float acc = 0.f;
    const int jrow = tid & 7;
    const int c0   = (tid >> 3) * 8;
    const u64* __restrict__ smq = (const u64*)sm;

    for (int chunk = 0; chunk < NCHUNK; ++chunk) {
        const int rb = r0 + chunk * 8;
        if (GUARD && rb > rmax) break;

        // ---- vertical: 8 rows, ring-buffered running sums ----
#pragma unroll
        for (int j = 0; j < 8; ++j) {
            int r = rb + j;
            if (!GUARD || r <= rmax) {
                float xn = xp[(r + 6) * IW + col];
                float yn = yp[(r + 6) * IW + col];
                Vx += xn; Vy += yn;
                Vs  = fmaf(xn, xn, Vs);
                Vs  = fmaf(yn, yn, Vs);
                Vxy = fmaf(xn, yn, Vxy);
                sm[j * RS2 + col]          = make_float2(Vx, Vy);
                sm[PLANE2 + j * RS2 + col] = make_float2(Vs, Vxy);
                float xo = rx[(j + 2) & 7];
                float yo = ry[(j + 2) & 7];
                Vx -= xo; Vy -= yo;
                Vs  = fmaf(xo, -xo, Vs);
                Vs  = fmaf(yo, -yo, Vs);
                Vxy = fmaf(xo, -yo, Vxy);
                rx[j] = xn; ry[j] = yn;
            }
        }
        __syncthreads();

        // ---- horizontal: packed 7-wide sliding window, 8 outputs/thread ----
        {
            int r = rb + jrow;
            if (!GUARD || r <= rmax) {
                const u64* __restrict__ p01 = smq + jrow * RS2 + c0;
                const u64* __restrict__ p23 = p01 + PLANE2;
                u64 B01 = p01[0];
                u64 B23 = p23[0];
#pragma unroll
                for (int k = 1; k < 7; ++k) {
                    B01 = add2(B01, p01[k]);
                    B23 = add2(B23, p23[k]);
                }
                float sx, sy, ss, sxy;
                unpack2(B01, sx, sy);
                unpack2(B23, ss, sxy);
                acc += ssim_term(sx, sy, ss, sxy);
                const int T = (OW - c0 < 8) ? (OW - c0) : 8;
#pragma unroll
                for (int i = 1; i < 8; ++i) {
                    if (i < T) {
                        B01 = add2(B01, p01[6 + i]);
                        B01 = fma2(p01[i - 1], NEG1X2, B01);
                        B23 = add2(B23, p23[6 + i]);
                        B23 = fma2(p23[i - 1], NEG1X2, B23);
                        unpack2(B01, sx, sy);
                        unpack2(B23, ss, sxy);
                        acc += ssim_term(sx, sy, ss, sxy);
                    }
                }
            }
        }
        __syncthreads();
    }
    return acc;
}

__global__ __launch_bounds__(512, 2)
void ssim_kernel(const float* __restrict__ X, const float* __restrict__ Y,
                 float* __restrict__ out) {
    extern __shared__ float2 smbuf[];
    __shared__ float wsum[16];
    __shared__ bool isLast;

    const int tid  = threadIdx.x;
    const int band = blockIdx.x;
    const int img  = blockIdx.y;

    const float* __restrict__ xp = X + (size_t)img * (512 * 512);
    const float* __restrict__ yp = Y + (size_t)img * (512 * 512);
    const int r0   = band * BR;
    const int rmax = min(r0 + BR - 1, OH - 1);

    float acc;
    if (r0 + NCHUNK * 8 - 1 <= rmax) {
        acc = process_band<false>(xp, yp, smbuf, r0, rmax, tid);
    } else {
        acc = process_band<true>(xp, yp, smbuf, r0, rmax, tid);
    }

    // ---- block reduction ----
#pragma unroll
    for (int o = 16; o > 0; o >>= 1)
        acc += __shfl_xor_sync(0xffffffffu, acc, o);
    if ((tid & 31) == 0) wsum[tid >> 5] = acc;
    __syncthreads();

    if (tid == 0) {
        float s = 0.f;
#pragma unroll
        for (int w = 0; w < 16; ++w) s += wsum[w];
        g_partials[img * NBANDS + band] = s;
        __threadfence();
        unsigned int old = atomicAdd(&g_count, 1u);
        isLast = (old == NCTA - 1);
    }
    __syncthreads();

    // ---- deterministic last-block global reduction ----
    if (isLast) {
        float s = 0.f;
        for (int i = tid; i < NCTA; i += 512) s += g_partials[i];
#pragma unroll
        for (int o = 16; o > 0; o >>= 1)
            s += __shfl_xor_sync(0xffffffffu, s, o);
        if ((tid & 31) == 0) wsum[tid >> 5] = s;
        __syncthreads();
        if (tid == 0) {
            float t = 0.f;
#pragma unroll
            for (int w = 0; w < 16; ++w) t += wsum[w];
            out[0] = 1.0f - t * (1.0f / 24579456.0f);  // 96*506*506
            g_count = 0;  // reset for next graph replay
        }
    }
}

extern "C" void kernel_launch(void* const* d_in, const int* in_sizes, int n_in,
                              void* d_out, int out_size) {
    (void)in_sizes; (void)n_in; (void)out_size;
    const float* X = (const float*)d_in[0];
    const float* Y = (const float*)d_in[1];

    cudaFuncSetAttribute(ssim_kernel,
                         cudaFuncAttributeMaxDynamicSharedMemorySize, SMEM_BYTES);

    dim3 grid(NBANDS, NIMG);
    ssim_kernel<<<grid, 512, SMEM_BYTES>>>(X, Y, (float*)d_out);
}

// round 4
// speedup vs baseline: 1.9660x; 1.3116x over previous
#include <cuda_runtime.h>

// SSIM loss, 7x7 valid window, [32,3,512,512] fp32, scalar out.
// R4: merged-phase double buffering. 4-row subchunks, two smem buffers; each
// barrier interval = [prefetch LDGs for t+1] + [horizontal(t)] + [vertical(t+1)]
// so DRAM latency of the vertical loads hides behind horizontal math.
// Packed f32x2 everywhere in the horizontal sliding window.

#define IW     512
#define OH     506
#define OW     506
#define BR     88
#define NBANDS 6
#define NIMG   96
#define NCTA   (NBANDS * NIMG)     // 576
#define RS2    517                 // float2 row stride (conflict-free)
#define PLANE4 (4 * RS2)           // one quantity plane, 4 rows (float2 units)
#define BUF2   (2 * PLANE4)        // one buffer: 2 planes (float2 units)
#define SMEM_BYTES (2 * BUF2 * 8)  // 66,176 B -> 2 CTAs/SM

typedef unsigned long long u64;

__device__ float g_partials[NCTA];
__device__ unsigned int g_count = 0;

__device__ __forceinline__ u64 add2(u64 a, u64 b) {
    u64 r; asm("add.rn.f32x2 %0, %1, %2;" : "=l"(r) : "l"(a), "l"(b)); return r;
}
__device__ __forceinline__ u64 fma2(u64 a, u64 b, u64 c) {
    u64 r; asm("fma.rn.f32x2 %0, %1, %2, %3;" : "=l"(r) : "l"(a), "l"(b), "l"(c)); return r;
}
__device__ __forceinline__ void unpack2(u64 v, float& a, float& b) {
    asm("mov.b64 {%0, %1}, %2;" : "=f"(a), "=f"(b) : "l"(v));
}
#define NEG1X2 0xBF800000BF800000ull

__device__ __forceinline__ float ssim_term(float sx, float sy, float ss, float sxy) {
    const float c1big = 0.2401f;   // 2401 * (0.01)^2
    const float c2big = 2.1168f;   // 2352 * (0.03)^2
    float t1 = sx * sy;
    float a1 = fmaf(t1, 2.0f, c1big);
    float b1 = fmaf(sx, sx, c1big);
    b1 = fmaf(sy, sy, b1);
    float a2 = fmaf(sxy, 98.0f, c2big);
    a2 = fmaf(t1, -2.0f, a2);
    float b2 = fmaf(ss, 49.0f, c2big);
    b2 = fmaf(sx, -sx, b2);
    b2 = fmaf(sy, -sy, b2);
    return __fdividef(a1 * a2, b1 * b2);
}

struct VState {
    float Vx, Vy, Vs, Vxy;
    float rx[8], ry[8];   // ring: static-indexed via template<PH>
};

// Vertical: 4 rows of subchunk starting at rb (rb % 8 == PH), inputs prefetched.
template <int PH, bool GUARD>
__device__ __forceinline__ void vert_step(
    VState& v, float2* __restrict__ buf, const float* nx, const float* ny,
    int rb, int rmax, int col) {
#pragma unroll
    for (int j = 0; j < 4; ++j) {
        if (!GUARD || rb + j <= rmax) {
            float xn = nx[j], yn = ny[j];
            v.Vx += xn; v.Vy += yn;
            v.Vs  = fmaf(xn, xn, v.Vs);
            v.Vs  = fmaf(yn, yn, v.Vs);
            v.Vxy = fmaf(xn, yn, v.Vxy);
            buf[j * RS2 + col]          = make_float2(v.Vx, v.Vy);
            buf[PLANE4 + j * RS2 + col] = make_float2(v.Vs, v.Vxy);
            float xo = v.rx[(PH + j) & 7];
            float yo = v.ry[(PH + j) & 7];
            v.Vx -= xo; v.Vy -= yo;
            v.Vs  = fmaf(xo, -xo, v.Vs);
            v.Vs  = fmaf(yo, -yo, v.Vs);
            v.Vxy = fmaf(xo, -yo, v.Vxy);
            v.rx[(PH + j + 6) & 7] = xn;
            v.ry[(PH + j + 6) & 7] = yn;
        }
    }
}

template <bool GUARD>
__device__ __forceinline__ void prefetch4(
    const float* __restrict__ xp, const float* __restrict__ yp,
    float* nx, float* ny, int rbn, int rmax, int col) {
#pragma unroll
    for (int j = 0; j < 4; ++j) {
        if (!GUARD || rbn + j <= rmax) {
            nx[j] = xp[(rbn + j + 6) * IW + col];
            ny[j] = yp[(rbn + j + 6) * IW + col];
        }
    }
}

// Horizontal: 4 outputs (1 row x 4 cols) from buffer, packed sliding window.
template <bool GUARD>
__device__ __forceinline__ void horiz_step(
    const u64* __restrict__ smq, int bufsel, int rb, int rmax,
    int jrow, int c0, float& acc) {
    bool rowok = (!GUARD || rb + jrow <= rmax) && (c0 < OW);
    if (rowok) {
        const u64* __restrict__ p01 = smq + (size_t)bufsel * BUF2 + jrow * RS2 + c0;
        const u64* __restrict__ p23 = p01 + PLANE4;
        u64 B01 = p01[0];
        u64 B23 = p23[0];
#pragma unroll
        for (int k = 1; k < 7; ++k) {
            B01 = add2(B01, p01[k]);
            B23 = add2(B23, p23[k]);
        }
        float sx, sy, ss, sxy;
        unpack2(B01, sx, sy);
        unpack2(B23, ss, sxy);
        acc += ssim_term(sx, sy, ss, sxy);
        const int T = (OW - c0 < 4) ? (OW - c0) : 4;
#pragma unroll
        for (int i = 1; i < 4; ++i) {
            if (i < T) {
                B01 = add2(B01, p01[6 + i]);
                B01 = fma2(p01[i - 1], NEG1X2, B01);
                B23 = add2(B23, p23[6 + i]);
                B23 = fma2(p23[i - 1], NEG1X2, B23);
                unpack2(B01, sx, sy);
                unpack2(B23, ss, sxy);
                acc += ssim_term(sx, sy, ss, sxy);
            }
        }
    }
}

template <bool GUARD>
__device__ __forceinline__ float process_band(
    const float* __restrict__ xp, const float* __restrict__ yp,
    float2* __restrict__ sm, int r0, int rmax, int tid) {

    const int col  = tid;
    const int jrow = tid & 3;
    const int c0   = (tid >> 2) * 4;
    const u64* smq = (const u64*)sm;

    VState v;
    v.Vx = 0.f; v.Vy = 0.f; v.Vs = 0.f; v.Vxy = 0.f;

    // prologue: rows r0..r0+5 (always in-bounds, even for tail band)
#pragma unroll
    for (int k = 0; k < 6; ++k) {
        float x = xp[(r0 + k) * IW + col];
        float y = yp[(r0 + k) * IW + col];
        v.Vx += x; v.Vy += y;
        v.Vs  = fmaf(x, x, v.Vs);
        v.Vs  = fmaf(y, y, v.Vs);
        v.Vxy = fmaf(x, y, v.Vxy);
        v.rx[k] = x; v.ry[k] = y;
    }

    // vertical subchunk 0 (rows r0..r0+3, always valid)
    {
        float nx[4], ny[4];
        prefetch4<false>(xp, yp, nx, ny, r0, rmax, col);
        vert_step<0, false>(v, sm, nx, ny, r0, rmax, col);
    }
    __syncthreads();

    const int nsub = GUARD ? (((rmax - r0) >> 2) + 1) : (BR / 4);
    float acc = 0.f;

    for (int t = 0; t + 1 < nsub; t += 2) {
        // iter A: horizontal(t) + vertical(t+1), rb_next % 8 == 4
        {
            const int rbn = r0 + (t + 1) * 4;
            float nx[4], ny[4];
            prefetch4<GUARD>(xp, yp, nx, ny, rbn, rmax, col);
            horiz_step<GUARD>(smq, t & 1, r0 + t * 4, rmax, jrow, c0, acc);
            vert_step<4, GUARD>(v, sm + (size_t)((t + 1) & 1) * BUF2,
                                nx, ny, rbn, rmax, col);
            __syncthreads();
        }
        // iter B: horizontal(t+1) + vertical(t+2), rb_next % 8 == 0
        if (t + 2 < nsub) {
            const int rbn = r0 + (t + 2) * 4;
            float nx[4], ny[4];
            prefetch4<GUARD>(xp, yp, nx, ny, rbn, rmax, col);
            horiz_step<GUARD>(smq, (t + 1) & 1, r0 + (t + 1) * 4, rmax, jrow, c0, acc);
            vert_step<0, GUARD>(v, sm + (size_t)((t + 2) & 1) * BUF2,
                                nx, ny, rbn, rmax, col);
            __syncthreads();
        }
    }
    // final horizontal
    horiz_step<GUARD>(smq, (nsub - 1) & 1, r0 + (nsub - 1) * 4, rmax, jrow, c0, acc);
    return acc;
}

__global__ __launch_bounds__(512, 2)
void ssim_kernel(const float* __restrict__ X, const float* __restrict__ Y,
                 float* __restrict__ out) {
    extern __shared__ float2 smbuf[];
    __shared__ float wsum[16];
    __shared__ bool isLast;

    const int tid  = threadIdx.x;
    const int band = blockIdx.x;
    const int img  = blockIdx.y;

    const float* __restrict__ xp = X + (size_t)img * (512 * 512);
    const float* __restrict__ yp = Y + (size_t)img * (512 * 512);
    const int r0   = band * BR;
    const int rmax = min(r0 + BR - 1, OH - 1);

    float acc;
    if (rmax == r0 + BR - 1) {
        acc = process_band<false>(xp, yp, smbuf, r0, rmax, tid);
    } else {
        acc = process_band<true>(xp, yp, smbuf, r0, rmax, tid);
    }

#pragma unroll
    for (int o = 16; o > 0; o >>= 1)
        acc += __shfl_xor_sync(0xffffffffu, acc, o);
    if ((tid & 31) == 0) wsum[tid >> 5] = acc;
    __syncthreads();

    if (tid == 0) {
        float s = 0.f;
#pragma unroll
        for (int w = 0; w < 16; ++w) s += wsum[w];
        g_partials[img * NBANDS + band] = s;
        __threadfence();
        unsigned int old = atomicAdd(&g_count, 1u);
        isLast = (old == NCTA - 1);
    }
    __syncthreads();

    if (isLast) {
        float s = 0.f;
        for (int i = tid; i < NCTA; i += 512) s += g_partials[i];
#pragma unroll
        for (int o = 16; o > 0; o >>= 1)
            s += __shfl_xor_sync(0xffffffffu, s, o);
        if ((tid & 31) == 0) wsum[tid >> 5] = s;
        __syncthreads();
        if (tid == 0) {
            float t = 0.f;
#pragma unroll
            for (int w = 0; w < 16; ++w) t += wsum[w];
            out[0] = 1.0f - t * (1.0f / 24579456.0f);  // 96*506*506
            g_count = 0;  // reset for next graph replay
        }
    }
}

extern "C" void kernel_launch(void* const* d_in, const int* in_sizes, int n_in,
                              void* d_out, int out_size) {
    (void)in_sizes; (void)n_in; (void)out_size;
    const float* X = (const float*)d_in[0];
    const float* Y = (const float*)d_in[1];

    cudaFuncSetAttribute(ssim_kernel,
                         cudaFuncAttributeMaxDynamicSharedMemorySize, SMEM_BYTES);

    dim3 grid(NBANDS, NIMG);
    ssim_kernel<<<grid, 512, SMEM_BYTES>>>(X, Y, (float*)d_out);
}